// round 15
// baseline (speedup 1.0000x reference)
#include <cuda_runtime.h>
#include <cuda_bf16.h>
#include <cuda_fp16.h>
#include <cstdint>

#define BATCH 4
#define SQ    4096
#define SKV   1024
#define DE    1024
#define DC    768
#define NH    16
#define DH    64
#define MQ    (BATCH * SQ)    // 16384
#define MKV   (BATCH * SKV)   // 4096

// ---------------- scratch (__device__ globals; no runtime alloc) -----------
__device__ __align__(16) __half g_x[(size_t)MQ * DE];       // fp16 single
__device__ __align__(16) __half g_y[(size_t)MKV * DC];      // fp16 single
__device__ __align__(16) __half g_Qh[(size_t)MQ * DE];      // fp16 hi (scaled)
__device__ __align__(16) __half g_Ql[(size_t)MQ * DE];      // fp16 lo (scaled)
__device__ __align__(16) __half g_K[(size_t)MKV * DE];      // fp16 single
__device__ __align__(16) __half g_V[(size_t)MKV * DE];      // fp16 single
__device__ __align__(16) __half g_c[(size_t)MQ * DE];       // fp16 single
__device__ __align__(16) __half g_Wq[(size_t)DE * DE];      // fp16 single, [N,K]
__device__ __align__(16) __half g_Wkv[(size_t)2 * DE * DC]; // fp16 single, [2N,K]
__device__ __align__(16) __half g_Wo[(size_t)DE * DE];      // fp16 single, [N,K]

// ---------------- PTX helpers ----------------------------------------------
__device__ __forceinline__ uint32_t smem_u32(const void* p) {
    uint32_t a;
    asm("{ .reg .u64 t; cvta.to.shared.u64 t, %1; cvt.u32.u64 %0, t; }"
        : "=r"(a) : "l"(p));
    return a;
}
__device__ __forceinline__ void cp16(uint32_t dst, const void* src) {
    asm volatile("cp.async.cg.shared.global [%0], [%1], 16;"
                 :: "r"(dst), "l"(src) : "memory");
}
#define CP_COMMIT() asm volatile("cp.async.commit_group;" ::: "memory")
#define CP_WAIT1()  asm volatile("cp.async.wait_group 1;" ::: "memory")
#define CP_WAIT0()  asm volatile("cp.async.wait_group 0;" ::: "memory")

#define LDSM4(r0, r1, r2, r3, addr) \
    asm volatile("ldmatrix.sync.aligned.m8n8.x4.shared.b16 {%0,%1,%2,%3}, [%4];" \
                 : "=r"(r0), "=r"(r1), "=r"(r2), "=r"(r3) : "r"(addr))
#define LDSM4T(r0, r1, r2, r3, addr) \
    asm volatile("ldmatrix.sync.aligned.m8n8.x4.trans.shared.b16 {%0,%1,%2,%3}, [%4];" \
                 : "=r"(r0), "=r"(r1), "=r"(r2), "=r"(r3) : "r"(addr))

#define MMAH16816(d, a, b) \
    asm volatile("mma.sync.aligned.m16n8k16.row.col.f32.f16.f16.f32 " \
                 "{%0,%1,%2,%3},{%4,%5,%6,%7},{%8,%9},{%0,%1,%2,%3};" \
                 : "+f"((d)[0]), "+f"((d)[1]), "+f"((d)[2]), "+f"((d)[3]) \
                 : "r"((a)[0]), "r"((a)[1]), "r"((a)[2]), "r"((a)[3]), \
                   "r"((b)[0]), "r"((b)[1]))

__device__ __forceinline__ void split_pair_h(float f0, float f1,
                                             uint32_t& h, uint32_t& l) {
    __half2 hb = __floats2half2_rn(f0, f1);
    float r0 = f0 - __low2float(hb);
    float r1 = f1 - __high2float(hb);
    __half2 lb = __floats2half2_rn(r0, r1);
    h = reinterpret_cast<uint32_t&>(hb);
    l = reinterpret_cast<uint32_t&>(lb);
}
__device__ __forceinline__ uint32_t h2u(float a, float b) {
    __half2 h = __floats2half2_rn(a, b);
    return reinterpret_cast<uint32_t&>(h);
}

// ---------------- conversion kernels ---------------------------------------
__global__ void k_half(const float* __restrict__ in,
                       __half* __restrict__ o, int n4)
{
    int i = blockIdx.x * blockDim.x + threadIdx.x;
    if (i >= n4) return;
    float4 v = reinterpret_cast<const float4*>(in)[i];
    reinterpret_cast<__half2*>(o)[2 * i]     = __floats2half2_rn(v.x, v.y);
    reinterpret_cast<__half2*>(o)[2 * i + 1] = __floats2half2_rn(v.z, v.w);
}

// W[K,N] -> Wt fp16 single [N,K]
__global__ void k_tsplit_h(const float* __restrict__ W,
                           __half* __restrict__ th, int Kd, int Nd)
{
    __shared__ float t[32][33];
    int n0 = blockIdx.x * 32, k0 = blockIdx.y * 32;
    int tx = threadIdx.x, ty = threadIdx.y;
    #pragma unroll
    for (int i = 0; i < 32; i += 8)
        t[ty + i][tx] = W[(size_t)(k0 + ty + i) * Nd + n0 + tx];
    __syncthreads();
    #pragma unroll
    for (int i = 0; i < 32; i += 8)
        th[(size_t)(n0 + ty + i) * Kd + k0 + tx] = __float2half(t[tx][ty + i]);
}

// ---------------- warp-mma 1-term fp16 GEMM ---------------------------------
// C = A @ B^T + bias ; A single fp16, B single fp16, fp32 accum.
// CTA 128x128, BK=64, 8 warps (2m x 4n), warp tile 64x32, 2 CTAs/SM.
// OUTM 0: C fp32 (+bias). OUTM 1: Ch/Cl fp16 hi/lo of (acc+bias)*scale.
// OUTM 2: KV single fp16 — n0<DE -> (bias, Ch), else (bias2, Ch2).
#define BM 128
#define BN 128
#define BK 64
#define OFF_A  0
#define OFF_B  16384
#define STAGE  32768
#define GEMM_SMEM (2 * STAGE)   // 65536; x2 CTAs = 128KB/SM

template <int OUTM>
__global__ __launch_bounds__(256, 2)
void gemm_mma(int M, int K,
              const __half* __restrict__ A,
              const __half* __restrict__ B,
              const float* __restrict__ bias, const float* __restrict__ bias2,
              float scale,
              float* __restrict__ C,
              uint16_t* __restrict__ Ch, uint16_t* __restrict__ Cl,
              uint16_t* __restrict__ Ch2)
{
    extern __shared__ __align__(128) char dsm[];
    const uint32_t sb = smem_u32(dsm);

    const int tid  = threadIdx.x;
    const int wid  = tid >> 5;
    const int lane = tid & 31;
    const int n0 = blockIdx.x * BN;
    const int m0 = blockIdx.y * BM;
    const int NC = K / BK;

    const int warp_m = (wid & 1) * 64;
    const int warp_n = (wid >> 1) * 32;

    float d[4][4][4];
    #pragma unroll
    for (int i = 0; i < 4; i++)
        #pragma unroll
        for (int j = 0; j < 4; j++)
            #pragma unroll
            for (int e = 0; e < 4; e++) d[i][j][e] = 0.0f;

    auto load_stage = [&](int buf, int kc) {
        uint32_t base = sb + (uint32_t)buf * STAGE;
        int k0 = kc * BK;
        #pragma unroll
        for (int t = 0; t < 4; t++) {               // A: 128 rows x 8 chunks
            int idx = tid + t * 256;
            int row = idx >> 3, ch = idx & 7;
            uint32_t sw = (uint32_t)(row * 128 + 16 * (ch ^ (row & 7)));
            size_t g = (size_t)(m0 + row) * K + k0 + ch * 8;
            cp16(base + OFF_A + sw, A + g);
        }
        #pragma unroll
        for (int t = 0; t < 4; t++) {               // B: 128 rows x 8 chunks
            int idx = tid + t * 256;
            int row = idx >> 3, ch = idx & 7;
            uint32_t sw = (uint32_t)(row * 128 + 16 * (ch ^ (row & 7)));
            size_t g = (size_t)(n0 + row) * K + k0 + ch * 8;
            cp16(base + OFF_B + sw, B + g);
        }
        CP_COMMIT();
    };

    const int aRowL = warp_m + (lane & 7) + ((lane >> 3) & 1) * 8;
    const int aCbit = (lane >> 4);
    const int bRowL = warp_n + (lane & 7) + ((lane >> 4) & 1) * 8;
    const int bCbit = (lane >> 3) & 1;

    load_stage(0, 0);

    for (int c = 0; c < NC; c++) {
        if (c + 1 < NC) { load_stage((c + 1) & 1, c + 1); CP_WAIT1(); }
        else            { CP_WAIT0(); }
        __syncthreads();

        uint32_t base = sb + (uint32_t)(c & 1) * STAGE;

        #pragma unroll
        for (int ks = 0; ks < 4; ks++) {
            uint32_t a[4][4];
            #pragma unroll
            for (int i = 0; i < 4; i++) {
                int row = aRowL + 16 * i;
                uint32_t off = (uint32_t)(row * 128 +
                               16 * ((2 * ks + aCbit) ^ (row & 7)));
                LDSM4(a[i][0], a[i][1], a[i][2], a[i][3], base + OFF_A + off);
            }
            #pragma unroll
            for (int j2 = 0; j2 < 2; j2++) {
                int row = bRowL + 16 * j2;
                uint32_t off = (uint32_t)(row * 128 +
                               16 * ((2 * ks + bCbit) ^ (row & 7)));
                uint32_t bq[2][2];
                LDSM4(bq[0][0], bq[0][1], bq[1][0], bq[1][1], base + OFF_B + off);
                #pragma unroll
                for (int i = 0; i < 4; i++) {
                    MMAH16816(d[i][2 * j2],     a[i], bq[0]);
                    MMAH16816(d[i][2 * j2 + 1], a[i], bq[1]);
                }
            }
        }
        __syncthreads();
    }

    // ---- epilogue ----
    const float* bb = bias;
    uint16_t* Dh = Ch;
    int ncol0 = n0;
    if (OUTM == 2 && n0 >= DE) {
        bb = bias2; Dh = Ch2; ncol0 = n0 - DE;
    }

    const int frow = lane >> 2;
    const int fcol = (lane & 3) * 2;
    #pragma unroll
    for (int j = 0; j < 4; j++) {
        int col = ncol0 + warp_n + 8 * j + fcol;
        float b0 = bb[col], b1 = bb[col + 1];
        #pragma unroll
        for (int i = 0; i < 4; i++) {
            int row = m0 + warp_m + 16 * i + frow;
            if (OUTM == 0) {
                float2 v0 = make_float2(d[i][j][0] + b0, d[i][j][1] + b1);
                float2 v1 = make_float2(d[i][j][2] + b0, d[i][j][3] + b1);
                *reinterpret_cast<float2*>(C + (size_t)row * DE + col)       = v0;
                *reinterpret_cast<float2*>(C + (size_t)(row + 8) * DE + col) = v1;
            } else if (OUTM == 2) {
                *reinterpret_cast<uint32_t*>(Dh + (size_t)row * DE + col) =
                    h2u(d[i][j][0] + b0, d[i][j][1] + b1);
                *reinterpret_cast<uint32_t*>(Dh + (size_t)(row + 8) * DE + col) =
                    h2u(d[i][j][2] + b0, d[i][j][3] + b1);
            } else {
                uint32_t h, l;
                split_pair_h((d[i][j][0] + b0) * scale, (d[i][j][1] + b1) * scale, h, l);
                *reinterpret_cast<uint32_t*>(Ch + (size_t)row * DE + col) = h;
                *reinterpret_cast<uint32_t*>(Cl + (size_t)row * DE + col) = l;
                split_pair_h((d[i][j][2] + b0) * scale, (d[i][j][3] + b1) * scale, h, l);
                *reinterpret_cast<uint32_t*>(Ch + (size_t)(row + 8) * DE + col) = h;
                *reinterpret_cast<uint32_t*>(Cl + (size_t)(row + 8) * DE + col) = l;
            }
        }
    }
}

// ---------------- flash attention via mma.sync (R13, known good) ------------
// CTA: 128 q rows x one (b,h). 8 warps x m16. 64-kv chunks, double buffered.
// S: 2-term (Q exact fp16 pair x K single). PV: 1-term (P fp16 x V fp16).
// ctx out: single fp16.
#define FBR 128
#define FBC 64
#define FNCH (SKV / FBC)
#define SQH 0
#define SQL 16384
#define SKV0 32768
#define SK_  0
#define SV_  8192
#define FSTG 16384
#define FLASH_SMEM (SKV0 + 2 * FSTG)   // 65536

__global__ __launch_bounds__(256, 2)
void flash_mma()
{
    extern __shared__ __align__(128) char fsm[];
    const uint32_t sb = smem_u32(fsm);
    const int tid = threadIdx.x, wid = tid >> 5, lane = tid & 31;
    const int qb = blockIdx.x, h = blockIdx.y, b = blockIdx.z;

    const size_t qrow0 = (size_t)b * SQ + (size_t)qb * FBR;
    const size_t krow0 = (size_t)b * SKV;
    const int colh = h * DH;

    #pragma unroll
    for (int t = 0; t < 4; t++) {
        int idx = tid + t * 256;
        int row = idx >> 3, ch = idx & 7;
        uint32_t sw = (uint32_t)(row * 128 + 16 * (ch ^ (row & 7)));
        size_t g = (qrow0 + row) * DE + colh + ch * 8;
        cp16(sb + SQH + sw, g_Qh + g);
        cp16(sb + SQL + sw, g_Ql + g);
    }
    #pragma unroll
    for (int t = 0; t < 2; t++) {
        int idx = tid + t * 256;
        int row = idx >> 3, ch = idx & 7;
        uint32_t sw = (uint32_t)(row * 128 + 16 * (ch ^ (row & 7)));
        size_t g = (krow0 + row) * DE + colh + ch * 8;
        cp16(sb + SKV0 + SK_ + sw, g_K + g);
        cp16(sb + SKV0 + SV_ + sw, g_V + g);
    }
    CP_COMMIT();
    CP_WAIT0();
    __syncthreads();

    const int aRow = wid * 16 + (lane & 7) + ((lane >> 3) & 1) * 8;
    const int aC = (lane >> 4) & 1;
    const int bRow = (lane & 7) + ((lane >> 4) & 1) * 8;
    const int bC = (lane >> 3) & 1;
    const int vRow = (lane & 7) + ((lane >> 3) & 1) * 8;
    const int vC = (lane >> 4) & 1;

    float m0 = -1e30f, m1 = -1e30f, l0 = 0.0f, l1 = 0.0f;
    float o[8][4];
    #pragma unroll
    for (int j = 0; j < 8; j++)
        #pragma unroll
        for (int e = 0; e < 4; e++) o[j][e] = 0.0f;

    for (int c = 0; c < FNCH; c++) {
        uint32_t stg = sb + SKV0 + (uint32_t)(c & 1) * FSTG;
        if (c + 1 < FNCH) {
            uint32_t nst = sb + SKV0 + (uint32_t)((c + 1) & 1) * FSTG;
            #pragma unroll
            for (int t = 0; t < 2; t++) {
                int idx = tid + t * 256;
                int row = idx >> 3, ch = idx & 7;
                uint32_t sw = (uint32_t)(row * 128 + 16 * (ch ^ (row & 7)));
                size_t g = (krow0 + (size_t)(c + 1) * FBC + row) * DE + colh + ch * 8;
                cp16(nst + SK_ + sw, g_K + g);
                cp16(nst + SV_ + sw, g_V + g);
            }
            CP_COMMIT();
        }

        // ---- S = Q K^T : 2-term fp16 ----
        float s[8][4];
        #pragma unroll
        for (int j = 0; j < 8; j++)
            #pragma unroll
            for (int e = 0; e < 4; e++) s[j][e] = 0.0f;

        #pragma unroll
        for (int ks = 0; ks < 4; ks++) {
            uint32_t qh[4], ql[4];
            uint32_t qoff = (uint32_t)(aRow * 128 + 16 * ((2 * ks + aC) ^ (aRow & 7)));
            LDSM4(qh[0], qh[1], qh[2], qh[3], sb + SQH + qoff);
            LDSM4(ql[0], ql[1], ql[2], ql[3], sb + SQL + qoff);
            #pragma unroll
            for (int np = 0; np < 4; np++) {
                int row = np * 16 + bRow;
                uint32_t off = (uint32_t)(row * 128 + 16 * ((2 * ks + bC) ^ (row & 7)));
                uint32_t kq[2][2];
                LDSM4(kq[0][0], kq[0][1], kq[1][0], kq[1][1], stg + SK_ + off);
                MMAH16816(s[2 * np],     qh, kq[0]);
                MMAH16816(s[2 * np],     ql, kq[0]);
                MMAH16816(s[2 * np + 1], qh, kq[1]);
                MMAH16816(s[2 * np + 1], ql, kq[1]);
            }
        }

        // ---- online softmax (fp32) ----
        float rm0 = -1e30f, rm1 = -1e30f;
        #pragma unroll
        for (int j = 0; j < 8; j++) {
            rm0 = fmaxf(rm0, fmaxf(s[j][0], s[j][1]));
            rm1 = fmaxf(rm1, fmaxf(s[j][2], s[j][3]));
        }
        rm0 = fmaxf(rm0, __shfl_xor_sync(0xffffffffu, rm0, 1));
        rm0 = fmaxf(rm0, __shfl_xor_sync(0xffffffffu, rm0, 2));
        rm1 = fmaxf(rm1, __shfl_xor_sync(0xffffffffu, rm1, 1));
        rm1 = fmaxf(rm1, __shfl_xor_sync(0xffffffffu, rm1, 2));

        float nm0 = fmaxf(m0, rm0), nm1 = fmaxf(m1, rm1);
        float cr0 = __expf(m0 - nm0), cr1 = __expf(m1 - nm1);
        m0 = nm0; m1 = nm1;

        float rs0 = 0.0f, rs1 = 0.0f;
        #pragma unroll
        for (int j = 0; j < 8; j++) {
            s[j][0] = __expf(s[j][0] - m0);
            s[j][1] = __expf(s[j][1] - m0);
            s[j][2] = __expf(s[j][2] - m1);
            s[j][3] = __expf(s[j][3] - m1);
            rs0 += s[j][0] + s[j][1];
            rs1 += s[j][2] + s[j][3];
        }
        rs0 += __shfl_xor_sync(0xffffffffu, rs0, 1);
        rs0 += __shfl_xor_sync(0xffffffffu, rs0, 2);
        rs1 += __shfl_xor_sync(0xffffffffu, rs1, 1);
        rs1 += __shfl_xor_sync(0xffffffffu, rs1, 2);
        l0 = l0 * cr0 + rs0;
        l1 = l1 * cr1 + rs1;

        #pragma unroll
        for (int j = 0; j < 8; j++) {
            o[j][0] *= cr0; o[j][1] *= cr0;
            o[j][2] *= cr1; o[j][3] *= cr1;
        }

        // ---- P -> single fp16 A-fragments ----
        uint32_t pf[4][4];
        #pragma unroll
        for (int ks = 0; ks < 4; ks++) {
            pf[ks][0] = h2u(s[2 * ks][0],     s[2 * ks][1]);
            pf[ks][1] = h2u(s[2 * ks][2],     s[2 * ks][3]);
            pf[ks][2] = h2u(s[2 * ks + 1][0], s[2 * ks + 1][1]);
            pf[ks][3] = h2u(s[2 * ks + 1][2], s[2 * ks + 1][3]);
        }

        // ---- O += P V : 1-term fp16 ----
        #pragma unroll
        for (int ks = 0; ks < 4; ks++) {
            #pragma unroll
            for (int dp = 0; dp < 4; dp++) {
                int row = ks * 16 + vRow;
                uint32_t off = (uint32_t)(row * 128 + 16 * ((2 * dp + vC) ^ (row & 7)));
                uint32_t vq[2][2];
                LDSM4T(vq[0][0], vq[0][1], vq[1][0], vq[1][1], stg + SV_ + off);
                MMAH16816(o[2 * dp],     pf[ks], vq[0]);
                MMAH16816(o[2 * dp + 1], pf[ks], vq[1]);
            }
        }

        if (c + 1 < FNCH) CP_WAIT0();
        __syncthreads();
    }

    // ---- epilogue: ctx single fp16 ----
    float inv0 = 1.0f / l0, inv1 = 1.0f / l1;
    size_t r0g = (qrow0 + wid * 16 + (lane >> 2)) * DE + colh;
    size_t r1g = r0g + (size_t)8 * DE;
    #pragma unroll
    for (int j = 0; j < 8; j++) {
        int col = 8 * j + (lane & 3) * 2;
        *reinterpret_cast<uint32_t*>(g_c + r0g + col) = h2u(o[j][0] * inv0, o[j][1] * inv0);
        *reinterpret_cast<uint32_t*>(g_c + r1g + col) = h2u(o[j][2] * inv1, o[j][3] * inv1);
    }
}

// ---------------------------------------------------------------------------
extern "C" void kernel_launch(void* const* d_in, const int* in_sizes, int n_in,
                              void* d_out, int out_size)
{
    const float* x  = (const float*)d_in[0];
    const float* y  = (const float*)d_in[1];
    const float* Wq = (const float*)d_in[2];
    const float* bq = (const float*)d_in[3];
    const float* Wk = (const float*)d_in[4];
    const float* bk = (const float*)d_in[5];
    const float* Wv = (const float*)d_in[6];
    const float* bv = (const float*)d_in[7];
    const float* Wo = (const float*)d_in[8];
    const float* bo = (const float*)d_in[9];
    float* out = (float*)d_out;
    (void)in_sizes; (void)n_in; (void)out_size;

    void *vx, *vy, *vc, *vQh, *vQl, *vK, *vV, *vWq, *vWkv, *vWo;
    cudaGetSymbolAddress(&vx,   g_x);
    cudaGetSymbolAddress(&vy,   g_y);
    cudaGetSymbolAddress(&vc,   g_c);
    cudaGetSymbolAddress(&vQh,  g_Qh);
    cudaGetSymbolAddress(&vQl,  g_Ql);
    cudaGetSymbolAddress(&vK,   g_K);
    cudaGetSymbolAddress(&vV,   g_V);
    cudaGetSymbolAddress(&vWq,  g_Wq);
    cudaGetSymbolAddress(&vWkv, g_Wkv);
    cudaGetSymbolAddress(&vWo,  g_Wo);

    __half* px   = (__half*)vx;
    __half* py   = (__half*)vy;
    __half* pc   = (__half*)vc;
    __half* pWq  = (__half*)vWq;
    __half* pWkv = (__half*)vWkv;
    __half* pWo  = (__half*)vWo;
    uint16_t* pQh = (uint16_t*)vQh;
    uint16_t* pQl = (uint16_t*)vQl;
    uint16_t* pK  = (uint16_t*)vK;
    uint16_t* pV  = (uint16_t*)vV;

    cudaFuncSetAttribute(gemm_mma<0>, cudaFuncAttributeMaxDynamicSharedMemorySize, GEMM_SMEM);
    cudaFuncSetAttribute(gemm_mma<1>, cudaFuncAttributeMaxDynamicSharedMemorySize, GEMM_SMEM);
    cudaFuncSetAttribute(gemm_mma<2>, cudaFuncAttributeMaxDynamicSharedMemorySize, GEMM_SMEM);
    cudaFuncSetAttribute(flash_mma, cudaFuncAttributeMaxDynamicSharedMemorySize, FLASH_SMEM);

    // convert inputs (fp16 single) + weights (fp16 single, transposed)
    k_half<<<(MQ * DE / 4 + 255) / 256, 256>>>(x, px, MQ * DE / 4);
    k_half<<<(MKV * DC / 4 + 255) / 256, 256>>>(y, py, MKV * DC / 4);
    k_tsplit_h<<<dim3(DE / 32, DE / 32), dim3(32, 8)>>>(Wq, pWq, DE, DE);
    k_tsplit_h<<<dim3(DE / 32, DC / 32), dim3(32, 8)>>>(Wk, pWkv, DC, DE);
    k_tsplit_h<<<dim3(DE / 32, DC / 32), dim3(32, 8)>>>(
        Wv, pWkv + (size_t)DE * DC, DC, DE);
    k_tsplit_h<<<dim3(DE / 32, DE / 32), dim3(32, 8)>>>(Wo, pWo, DE, DE);

    // Q projection -> fp16 hi/lo pair (exact split of accum), pre-scaled
    gemm_mma<1><<<dim3(DE / BN, MQ / BM), 256, GEMM_SMEM>>>(
        MQ, DE, px, pWq, bq, nullptr, 0.125f,
        nullptr, pQh, pQl, nullptr);
    // fused K+V projection (N = 2048): both single fp16
    gemm_mma<2><<<dim3(2 * DE / BN, MKV / BM), 256, GEMM_SMEM>>>(
        MKV, DC, py, pWkv, bk, bv, 1.0f,
        nullptr, pK, nullptr, pV);

    // attention -> ctx single fp16
    flash_mma<<<dim3(SQ / FBR, NH, BATCH), 256, FLASH_SMEM>>>();

    // output projection -> fp32 out
    gemm_mma<0><<<dim3(DE / BN, MQ / BM), 256, GEMM_SMEM>>>(
        MQ, DE, pc, pWo, bo, nullptr, 1.0f,
        out, nullptr, nullptr, nullptr);
}

// round 16
// speedup vs baseline: 1.6026x; 1.6026x over previous
#include <cuda_runtime.h>
#include <cuda_bf16.h>
#include <cuda_fp16.h>
#include <cstdint>

#define BATCH 4
#define SQ    4096
#define SKV   1024
#define DE    1024
#define DC    768
#define NH    16
#define DH    64
#define MQ    (BATCH * SQ)    // 16384
#define MKV   (BATCH * SKV)   // 4096

// ---------------- scratch (__device__ globals; no runtime alloc) -----------
__device__ __align__(16) __half g_x[(size_t)MQ * DE];       // fp16 single
__device__ __align__(16) __half g_y[(size_t)MKV * DC];      // fp16 single
__device__ __align__(16) __half g_Q[(size_t)MQ * DE];       // fp16 single (scaled)
__device__ __align__(16) __half g_K[(size_t)MKV * DE];      // fp16 single
__device__ __align__(16) __half g_V[(size_t)MKV * DE];      // fp16 single
__device__ __align__(16) __half g_c[(size_t)MQ * DE];       // fp16 single
__device__ __align__(16) __half g_Wq[(size_t)DE * DE];      // fp16 single, [N,K]
__device__ __align__(16) __half g_Wkv[(size_t)2 * DE * DC]; // fp16 single, [2N,K]
__device__ __align__(16) __half g_Wo[(size_t)DE * DE];      // fp16 single, [N,K]

// ---------------- PTX helpers ----------------------------------------------
__device__ __forceinline__ uint32_t smem_u32(const void* p) {
    uint32_t a;
    asm("{ .reg .u64 t; cvta.to.shared.u64 t, %1; cvt.u32.u64 %0, t; }"
        : "=r"(a) : "l"(p));
    return a;
}
__device__ __forceinline__ void cp16(uint32_t dst, const void* src) {
    asm volatile("cp.async.cg.shared.global [%0], [%1], 16;"
                 :: "r"(dst), "l"(src) : "memory");
}
#define CP_COMMIT() asm volatile("cp.async.commit_group;" ::: "memory")
#define CP_WAIT1()  asm volatile("cp.async.wait_group 1;" ::: "memory")
#define CP_WAIT0()  asm volatile("cp.async.wait_group 0;" ::: "memory")

#define LDSM4(r0, r1, r2, r3, addr) \
    asm volatile("ldmatrix.sync.aligned.m8n8.x4.shared.b16 {%0,%1,%2,%3}, [%4];" \
                 : "=r"(r0), "=r"(r1), "=r"(r2), "=r"(r3) : "r"(addr))
#define LDSM4T(r0, r1, r2, r3, addr) \
    asm volatile("ldmatrix.sync.aligned.m8n8.x4.trans.shared.b16 {%0,%1,%2,%3}, [%4];" \
                 : "=r"(r0), "=r"(r1), "=r"(r2), "=r"(r3) : "r"(addr))

#define MMAH16816(d, a, b) \
    asm volatile("mma.sync.aligned.m16n8k16.row.col.f32.f16.f16.f32 " \
                 "{%0,%1,%2,%3},{%4,%5,%6,%7},{%8,%9},{%0,%1,%2,%3};" \
                 : "+f"((d)[0]), "+f"((d)[1]), "+f"((d)[2]), "+f"((d)[3]) \
                 : "r"((a)[0]), "r"((a)[1]), "r"((a)[2]), "r"((a)[3]), \
                   "r"((b)[0]), "r"((b)[1]))

__device__ __forceinline__ uint32_t h2u(float a, float b) {
    __half2 h = __floats2half2_rn(a, b);
    return reinterpret_cast<uint32_t&>(h);
}

// ---------------- conversion kernels ---------------------------------------
__global__ void k_half(const float* __restrict__ in,
                       __half* __restrict__ o, int n4)
{
    int i = blockIdx.x * blockDim.x + threadIdx.x;
    if (i >= n4) return;
    float4 v = reinterpret_cast<const float4*>(in)[i];
    reinterpret_cast<__half2*>(o)[2 * i]     = __floats2half2_rn(v.x, v.y);
    reinterpret_cast<__half2*>(o)[2 * i + 1] = __floats2half2_rn(v.z, v.w);
}

// W[K,N] -> Wt fp16 single [N,K]
__global__ void k_tsplit_h(const float* __restrict__ W,
                           __half* __restrict__ th, int Kd, int Nd)
{
    __shared__ float t[32][33];
    int n0 = blockIdx.x * 32, k0 = blockIdx.y * 32;
    int tx = threadIdx.x, ty = threadIdx.y;
    #pragma unroll
    for (int i = 0; i < 32; i += 8)
        t[ty + i][tx] = W[(size_t)(k0 + ty + i) * Nd + n0 + tx];
    __syncthreads();
    #pragma unroll
    for (int i = 0; i < 32; i += 8)
        th[(size_t)(n0 + ty + i) * Kd + k0 + tx] = __float2half(t[tx][ty + i]);
}

// ---------------- warp-mma 1-term fp16 GEMM (R13 geometry, known good) ------
// C = A @ B^T + bias ; A single fp16, B single fp16, fp32 accum.
// CTA 64x128, BK=64, 8 warps (2m x 4n), warp tile 32x32, 2 CTAs/SM.
// OUTM 0: C fp32 (+bias). OUTM 1: Ch fp16 single of (acc+bias)*scale.
// OUTM 2: KV single fp16 — n0<DE -> (bias, Ch), else (bias2, Ch2).
#define BM 64
#define BN 128
#define BK 64
#define OFF_A  0
#define OFF_B  8192
#define STAGE  24576
#define GEMM_SMEM (2 * STAGE)   // 49152; x2 CTAs = 96KB/SM

template <int OUTM>
__global__ __launch_bounds__(256, 2)
void gemm_mma(int M, int K,
              const __half* __restrict__ A,
              const __half* __restrict__ B,
              const float* __restrict__ bias, const float* __restrict__ bias2,
              float scale,
              float* __restrict__ C,
              uint16_t* __restrict__ Ch,
              uint16_t* __restrict__ Ch2)
{
    extern __shared__ __align__(128) char dsm[];
    const uint32_t sb = smem_u32(dsm);

    const int tid  = threadIdx.x;
    const int wid  = tid >> 5;
    const int lane = tid & 31;
    const int n0 = blockIdx.x * BN;
    const int m0 = blockIdx.y * BM;
    const int NC = K / BK;

    const int warp_m = (wid & 1) * 32;
    const int warp_n = (wid >> 1) * 32;

    float d[2][4][4];
    #pragma unroll
    for (int i = 0; i < 2; i++)
        #pragma unroll
        for (int j = 0; j < 4; j++)
            #pragma unroll
            for (int e = 0; e < 4; e++) d[i][j][e] = 0.0f;

    auto load_stage = [&](int buf, int kc) {
        uint32_t base = sb + (uint32_t)buf * STAGE;
        int k0 = kc * BK;
        #pragma unroll
        for (int t = 0; t < 2; t++) {               // A: 64 rows x 8 chunks
            int idx = tid + t * 256;
            int row = idx >> 3, ch = idx & 7;
            uint32_t sw = (uint32_t)(row * 128 + 16 * (ch ^ (row & 7)));
            size_t g = (size_t)(m0 + row) * K + k0 + ch * 8;
            cp16(base + OFF_A + sw, A + g);
        }
        #pragma unroll
        for (int t = 0; t < 4; t++) {               // B: 128 rows x 8 chunks
            int idx = tid + t * 256;
            int row = idx >> 3, ch = idx & 7;
            uint32_t sw = (uint32_t)(row * 128 + 16 * (ch ^ (row & 7)));
            size_t g = (size_t)(n0 + row) * K + k0 + ch * 8;
            cp16(base + OFF_B + sw, B + g);
        }
        CP_COMMIT();
    };

    const int aRowL = warp_m + (lane & 7) + ((lane >> 3) & 1) * 8;
    const int aCbit = (lane >> 4);
    const int bRowL = warp_n + (lane & 7) + ((lane >> 4) & 1) * 8;
    const int bCbit = (lane >> 3) & 1;

    load_stage(0, 0);

    for (int c = 0; c < NC; c++) {
        if (c + 1 < NC) { load_stage((c + 1) & 1, c + 1); CP_WAIT1(); }
        else            { CP_WAIT0(); }
        __syncthreads();

        uint32_t base = sb + (uint32_t)(c & 1) * STAGE;

        #pragma unroll
        for (int ks = 0; ks < 4; ks++) {
            uint32_t a[2][4];
            #pragma unroll
            for (int i = 0; i < 2; i++) {
                int row = aRowL + 16 * i;
                uint32_t off = (uint32_t)(row * 128 +
                               16 * ((2 * ks + aCbit) ^ (row & 7)));
                LDSM4(a[i][0], a[i][1], a[i][2], a[i][3], base + OFF_A + off);
            }
            #pragma unroll
            for (int j2 = 0; j2 < 2; j2++) {
                int row = bRowL + 16 * j2;
                uint32_t off = (uint32_t)(row * 128 +
                               16 * ((2 * ks + bCbit) ^ (row & 7)));
                uint32_t bq[2][2];
                LDSM4(bq[0][0], bq[0][1], bq[1][0], bq[1][1], base + OFF_B + off);
                #pragma unroll
                for (int i = 0; i < 2; i++) {
                    MMAH16816(d[i][2 * j2],     a[i], bq[0]);
                    MMAH16816(d[i][2 * j2 + 1], a[i], bq[1]);
                }
            }
        }
        __syncthreads();
    }

    // ---- epilogue ----
    const float* bb = bias;
    uint16_t* Dh = Ch;
    int ncol0 = n0;
    if (OUTM == 2 && n0 >= DE) {
        bb = bias2; Dh = Ch2; ncol0 = n0 - DE;
    }

    const int frow = lane >> 2;
    const int fcol = (lane & 3) * 2;
    #pragma unroll
    for (int j = 0; j < 4; j++) {
        int col = ncol0 + warp_n + 8 * j + fcol;
        float b0 = bb[col], b1 = bb[col + 1];
        #pragma unroll
        for (int i = 0; i < 2; i++) {
            int row = m0 + warp_m + 16 * i + frow;
            if (OUTM == 0) {
                float2 v0 = make_float2(d[i][j][0] + b0, d[i][j][1] + b1);
                float2 v1 = make_float2(d[i][j][2] + b0, d[i][j][3] + b1);
                *reinterpret_cast<float2*>(C + (size_t)row * DE + col)       = v0;
                *reinterpret_cast<float2*>(C + (size_t)(row + 8) * DE + col) = v1;
            } else {
                *reinterpret_cast<uint32_t*>(Dh + (size_t)row * DE + col) =
                    h2u((d[i][j][0] + b0) * scale, (d[i][j][1] + b1) * scale);
                *reinterpret_cast<uint32_t*>(Dh + (size_t)(row + 8) * DE + col) =
                    h2u((d[i][j][2] + b0) * scale, (d[i][j][3] + b1) * scale);
            }
        }
    }
}

// ---------------- flash attention via mma.sync (all fp16, 1-term S) ---------
// CTA: 128 q rows x one (b,h). 8 warps x m16. 64-kv chunks, double buffered.
// S: 1-term (Q fp16 x K fp16). PV: 1-term (P fp16 x V fp16). ctx: single fp16.
#define FBR 128
#define FBC 64
#define FNCH (SKV / FBC)
#define SQ_  0
#define SKV0 16384
#define SK_  0
#define SV_  8192
#define FSTG 16384
#define FLASH_SMEM (SKV0 + 2 * FSTG)   // 49152

__global__ __launch_bounds__(256, 2)
void flash_mma()
{
    extern __shared__ __align__(128) char fsm[];
    const uint32_t sb = smem_u32(fsm);
    const int tid = threadIdx.x, wid = tid >> 5, lane = tid & 31;
    const int qb = blockIdx.x, h = blockIdx.y, b = blockIdx.z;

    const size_t qrow0 = (size_t)b * SQ + (size_t)qb * FBR;
    const size_t krow0 = (size_t)b * SKV;
    const int colh = h * DH;

    #pragma unroll
    for (int t = 0; t < 4; t++) {
        int idx = tid + t * 256;
        int row = idx >> 3, ch = idx & 7;
        uint32_t sw = (uint32_t)(row * 128 + 16 * (ch ^ (row & 7)));
        size_t g = (qrow0 + row) * DE + colh + ch * 8;
        cp16(sb + SQ_ + sw, g_Q + g);
    }
    #pragma unroll
    for (int t = 0; t < 2; t++) {
        int idx = tid + t * 256;
        int row = idx >> 3, ch = idx & 7;
        uint32_t sw = (uint32_t)(row * 128 + 16 * (ch ^ (row & 7)));
        size_t g = (krow0 + row) * DE + colh + ch * 8;
        cp16(sb + SKV0 + SK_ + sw, g_K + g);
        cp16(sb + SKV0 + SV_ + sw, g_V + g);
    }
    CP_COMMIT();
    CP_WAIT0();
    __syncthreads();

    const int aRow = wid * 16 + (lane & 7) + ((lane >> 3) & 1) * 8;
    const int aC = (lane >> 4) & 1;
    const int bRow = (lane & 7) + ((lane >> 4) & 1) * 8;
    const int bC = (lane >> 3) & 1;
    const int vRow = (lane & 7) + ((lane >> 3) & 1) * 8;
    const int vC = (lane >> 4) & 1;

    // Q fragments register-resident (single limb now — fits easily)
    uint32_t qf[4][4];
    #pragma unroll
    for (int ks = 0; ks < 4; ks++) {
        uint32_t qoff = (uint32_t)(aRow * 128 + 16 * ((2 * ks + aC) ^ (aRow & 7)));
        LDSM4(qf[ks][0], qf[ks][1], qf[ks][2], qf[ks][3], sb + SQ_ + qoff);
    }

    float m0 = -1e30f, m1 = -1e30f, l0 = 0.0f, l1 = 0.0f;
    float o[8][4];
    #pragma unroll
    for (int j = 0; j < 8; j++)
        #pragma unroll
        for (int e = 0; e < 4; e++) o[j][e] = 0.0f;

    for (int c = 0; c < FNCH; c++) {
        uint32_t stg = sb + SKV0 + (uint32_t)(c & 1) * FSTG;
        if (c + 1 < FNCH) {
            uint32_t nst = sb + SKV0 + (uint32_t)((c + 1) & 1) * FSTG;
            #pragma unroll
            for (int t = 0; t < 2; t++) {
                int idx = tid + t * 256;
                int row = idx >> 3, ch = idx & 7;
                uint32_t sw = (uint32_t)(row * 128 + 16 * (ch ^ (row & 7)));
                size_t g = (krow0 + (size_t)(c + 1) * FBC + row) * DE + colh + ch * 8;
                cp16(nst + SK_ + sw, g_K + g);
                cp16(nst + SV_ + sw, g_V + g);
            }
            CP_COMMIT();
        }

        // ---- S = Q K^T : 1-term fp16 ----
        float s[8][4];
        #pragma unroll
        for (int j = 0; j < 8; j++)
            #pragma unroll
            for (int e = 0; e < 4; e++) s[j][e] = 0.0f;

        #pragma unroll
        for (int ks = 0; ks < 4; ks++) {
            #pragma unroll
            for (int np = 0; np < 4; np++) {
                int row = np * 16 + bRow;
                uint32_t off = (uint32_t)(row * 128 + 16 * ((2 * ks + bC) ^ (row & 7)));
                uint32_t kq[2][2];
                LDSM4(kq[0][0], kq[0][1], kq[1][0], kq[1][1], stg + SK_ + off);
                MMAH16816(s[2 * np],     qf[ks], kq[0]);
                MMAH16816(s[2 * np + 1], qf[ks], kq[1]);
            }
        }

        // ---- online softmax (fp32) ----
        float rm0 = -1e30f, rm1 = -1e30f;
        #pragma unroll
        for (int j = 0; j < 8; j++) {
            rm0 = fmaxf(rm0, fmaxf(s[j][0], s[j][1]));
            rm1 = fmaxf(rm1, fmaxf(s[j][2], s[j][3]));
        }
        rm0 = fmaxf(rm0, __shfl_xor_sync(0xffffffffu, rm0, 1));
        rm0 = fmaxf(rm0, __shfl_xor_sync(0xffffffffu, rm0, 2));
        rm1 = fmaxf(rm1, __shfl_xor_sync(0xffffffffu, rm1, 1));
        rm1 = fmaxf(rm1, __shfl_xor_sync(0xffffffffu, rm1, 2));

        float nm0 = fmaxf(m0, rm0), nm1 = fmaxf(m1, rm1);
        float cr0 = __expf(m0 - nm0), cr1 = __expf(m1 - nm1);
        m0 = nm0; m1 = nm1;

        float rs0 = 0.0f, rs1 = 0.0f;
        #pragma unroll
        for (int j = 0; j < 8; j++) {
            s[j][0] = __expf(s[j][0] - m0);
            s[j][1] = __expf(s[j][1] - m0);
            s[j][2] = __expf(s[j][2] - m1);
            s[j][3] = __expf(s[j][3] - m1);
            rs0 += s[j][0] + s[j][1];
            rs1 += s[j][2] + s[j][3];
        }
        rs0 += __shfl_xor_sync(0xffffffffu, rs0, 1);
        rs0 += __shfl_xor_sync(0xffffffffu, rs0, 2);
        rs1 += __shfl_xor_sync(0xffffffffu, rs1, 1);
        rs1 += __shfl_xor_sync(0xffffffffu, rs1, 2);
        l0 = l0 * cr0 + rs0;
        l1 = l1 * cr1 + rs1;

        #pragma unroll
        for (int j = 0; j < 8; j++) {
            o[j][0] *= cr0; o[j][1] *= cr0;
            o[j][2] *= cr1; o[j][3] *= cr1;
        }

        // ---- P -> single fp16 A-fragments ----
        uint32_t pf[4][4];
        #pragma unroll
        for (int ks = 0; ks < 4; ks++) {
            pf[ks][0] = h2u(s[2 * ks][0],     s[2 * ks][1]);
            pf[ks][1] = h2u(s[2 * ks][2],     s[2 * ks][3]);
            pf[ks][2] = h2u(s[2 * ks + 1][0], s[2 * ks + 1][1]);
            pf[ks][3] = h2u(s[2 * ks + 1][2], s[2 * ks + 1][3]);
        }

        // ---- O += P V : 1-term fp16 ----
        #pragma unroll
        for (int ks = 0; ks < 4; ks++) {
            #pragma unroll
            for (int dp = 0; dp < 4; dp++) {
                int row = ks * 16 + vRow;
                uint32_t off = (uint32_t)(row * 128 + 16 * ((2 * dp + vC) ^ (row & 7)));
                uint32_t vq[2][2];
                LDSM4T(vq[0][0], vq[0][1], vq[1][0], vq[1][1], stg + SV_ + off);
                MMAH16816(o[2 * dp],     pf[ks], vq[0]);
                MMAH16816(o[2 * dp + 1], pf[ks], vq[1]);
            }
        }

        if (c + 1 < FNCH) CP_WAIT0();
        __syncthreads();
    }

    // ---- epilogue: ctx single fp16 ----
    float inv0 = 1.0f / l0, inv1 = 1.0f / l1;
    size_t r0g = (qrow0 + wid * 16 + (lane >> 2)) * DE + colh;
    size_t r1g = r0g + (size_t)8 * DE;
    #pragma unroll
    for (int j = 0; j < 8; j++) {
        int col = 8 * j + (lane & 3) * 2;
        *reinterpret_cast<uint32_t*>(g_c + r0g + col) = h2u(o[j][0] * inv0, o[j][1] * inv0);
        *reinterpret_cast<uint32_t*>(g_c + r1g + col) = h2u(o[j][2] * inv1, o[j][3] * inv1);
    }
}

// ---------------------------------------------------------------------------
extern "C" void kernel_launch(void* const* d_in, const int* in_sizes, int n_in,
                              void* d_out, int out_size)
{
    const float* x  = (const float*)d_in[0];
    const float* y  = (const float*)d_in[1];
    const float* Wq = (const float*)d_in[2];
    const float* bq = (const float*)d_in[3];
    const float* Wk = (const float*)d_in[4];
    const float* bk = (const float*)d_in[5];
    const float* Wv = (const float*)d_in[6];
    const float* bv = (const float*)d_in[7];
    const float* Wo = (const float*)d_in[8];
    const float* bo = (const float*)d_in[9];
    float* out = (float*)d_out;
    (void)in_sizes; (void)n_in; (void)out_size;

    void *vx, *vy, *vc, *vQ, *vK, *vV, *vWq, *vWkv, *vWo;
    cudaGetSymbolAddress(&vx,   g_x);
    cudaGetSymbolAddress(&vy,   g_y);
    cudaGetSymbolAddress(&vc,   g_c);
    cudaGetSymbolAddress(&vQ,   g_Q);
    cudaGetSymbolAddress(&vK,   g_K);
    cudaGetSymbolAddress(&vV,   g_V);
    cudaGetSymbolAddress(&vWq,  g_Wq);
    cudaGetSymbolAddress(&vWkv, g_Wkv);
    cudaGetSymbolAddress(&vWo,  g_Wo);

    __half* px   = (__half*)vx;
    __half* py   = (__half*)vy;
    __half* pc   = (__half*)vc;
    __half* pWq  = (__half*)vWq;
    __half* pWkv = (__half*)vWkv;
    __half* pWo  = (__half*)vWo;
    uint16_t* pQ = (uint16_t*)vQ;
    uint16_t* pK = (uint16_t*)vK;
    uint16_t* pV = (uint16_t*)vV;

    cudaFuncSetAttribute(gemm_mma<0>, cudaFuncAttributeMaxDynamicSharedMemorySize, GEMM_SMEM);
    cudaFuncSetAttribute(gemm_mma<1>, cudaFuncAttributeMaxDynamicSharedMemorySize, GEMM_SMEM);
    cudaFuncSetAttribute(gemm_mma<2>, cudaFuncAttributeMaxDynamicSharedMemorySize, GEMM_SMEM);
    cudaFuncSetAttribute(flash_mma, cudaFuncAttributeMaxDynamicSharedMemorySize, FLASH_SMEM);

    // convert inputs (fp16 single) + weights (fp16 single, transposed)
    k_half<<<(MQ * DE / 4 + 255) / 256, 256>>>(x, px, MQ * DE / 4);
    k_half<<<(MKV * DC / 4 + 255) / 256, 256>>>(y, py, MKV * DC / 4);
    k_tsplit_h<<<dim3(DE / 32, DE / 32), dim3(32, 8)>>>(Wq, pWq, DE, DE);
    k_tsplit_h<<<dim3(DE / 32, DC / 32), dim3(32, 8)>>>(Wk, pWkv, DC, DE);
    k_tsplit_h<<<dim3(DE / 32, DC / 32), dim3(32, 8)>>>(
        Wv, pWkv + (size_t)DE * DC, DC, DE);
    k_tsplit_h<<<dim3(DE / 32, DE / 32), dim3(32, 8)>>>(Wo, pWo, DE, DE);

    // Q projection -> single fp16, pre-scaled by 1/sqrt(dh)
    gemm_mma<1><<<dim3(DE / BN, MQ / BM), 256, GEMM_SMEM>>>(
        MQ, DE, px, pWq, bq, nullptr, 0.125f,
        nullptr, pQ, nullptr);
    // fused K+V projection (N = 2048): both single fp16
    gemm_mma<2><<<dim3(2 * DE / BN, MKV / BM), 256, GEMM_SMEM>>>(
        MKV, DC, py, pWkv, bk, bv, 1.0f,
        nullptr, pK, pV);

    // attention -> ctx single fp16
    flash_mma<<<dim3(SQ / FBR, NH, BATCH), 256, FLASH_SMEM>>>();

    // output projection -> fp32 out
    gemm_mma<0><<<dim3(DE / BN, MQ / BM), 256, GEMM_SMEM>>>(
        MQ, DE, pc, pWo, bo, nullptr, 1.0f,
        out, nullptr, nullptr);
}